// round 2
// baseline (speedup 1.0000x reference)
#include <cuda_runtime.h>
#include <cstdint>
#include <cstdio>

// Problem constants
#define N_TOK 32768      // tokens = 32 * 32 * 32
#define KCODE 8192       // codebook size
#define CDIM  256        // token size
#define NE    8388608    // total elements of x (32*256*32*32)

// Output layout (concatenated, all float32):
// x_quantized [8388608], loss [1], perplexity [1],
// min_encodings [32768*8192], min_encoding_indices [32768]
#define XQ_OFF   0
#define LOSS_OFF 8388608ULL
#define PERP_OFF 8388609ULL
#define OH_OFF   8388610ULL
#define IDX_OFF  276824066ULL

// Scratch (no device allocation allowed -> __device__ globals)
__device__ float  g_se2[KCODE];     // sum_c e^2 per code (fp32, like jnp.sum)
__device__ float  g_sx2[N_TOK];     // sum_c x^2 per token (fp32)
__device__ int    g_idx[N_TOK];     // argmin index per token
__device__ int    g_hist[KCODE];    // histogram of selected codes
__device__ double g_part[8192 * 2]; // per-block loss partials (sum diff, sum diff^2)

// ---------------------------------------------------------------------------
__global__ void k_init() {
    int t = threadIdx.x;
    for (int i = t; i < KCODE; i += blockDim.x) g_hist[i] = 0;
}

// sum of squares per codebook row: one warp per code
__global__ void k_se2(const float* __restrict__ cb) {
    int gw = (blockIdx.x * blockDim.x + threadIdx.x) >> 5;  // global warp = code
    int lane = threadIdx.x & 31;
    if (gw >= KCODE) return;
    const float* row = cb + (size_t)gw * CDIM;
    float s = 0.f;
#pragma unroll
    for (int w = 0; w < 8; w++) { float v = row[lane + w * 32]; s += v * v; }
#pragma unroll
    for (int o = 16; o > 0; o >>= 1) s += __shfl_down_sync(0xffffffffu, s, o);
    if (lane == 0) g_se2[gw] = s;
}

// sum of squares per token (x layout [B,C,H,W]; token n = b*1024 + hw, feature
// c at x[b*262144 + c*1024 + hw]) -- coalesced across consecutive n.
__global__ void k_sx2(const float* __restrict__ x) {
    int n = blockIdx.x * blockDim.x + threadIdx.x;
    if (n >= N_TOK) return;
    int b = n >> 10, hw = n & 1023;
    const float* px = x + (size_t)b * 262144 + hw;
    float s = 0.f;
#pragma unroll 8
    for (int c = 0; c < CDIM; c++) { float v = px[c * 1024]; s += v * v; }
    g_sx2[n] = s;
}

// ---------------------------------------------------------------------------
// Main distance GEMM + argmin. Tile: 128 tokens x 128 codes per CTA,
// 256 threads, 8x8 micro-tiles, C=256 reduction.
// Full x tile kept in smem (128 KB); codebook streamed in 64-c chunks.
#define TM 128
#define TN 128
#define ES_STR 132                      // 128 + 4 pad (16B-aligned rows)
#define SMEM_MAIN (256 * 128 * 4 + 64 * ES_STR * 4)   // 131072 + 33792 = 164864

extern __shared__ float smem[];

__global__ __launch_bounds__(256, 1)
void k_main(const float* __restrict__ x, const float* __restrict__ cb,
            float* __restrict__ out) {
    float* xs = smem;               // [256][128] : xs[c][m]
    float* es = smem + 256 * 128;   // [64][ES_STR] : es[c'][kk]

    int tid = threadIdx.x;
    int tx = tid & 15, ty = tid >> 4;
    int m0 = blockIdx.x * TM;                    // 1024 % 128 == 0 -> single b
    int bb = m0 >> 10, hw0 = m0 & 1023;
    const float* px = x + (size_t)bb * 262144 + hw0;

    // Load x tile into smem, transposed to [c][m]; coalesced float4 loads.
#pragma unroll 4
    for (int i = 0; i < 32; i++) {
        int idx4 = tid + i * 256;                // 0..8191 float4s
        int c = idx4 >> 5, m4 = (idx4 & 31) * 4;
        float4 v = *(const float4*)(px + c * 1024 + m4);
        *(float4*)(xs + c * 128 + m4) = v;
    }

    float sx2v[8];
#pragma unroll
    for (int i = 0; i < 8; i++) sx2v[i] = g_sx2[m0 + ty * 8 + i];

    float bestd[8]; int bestk[8];
#pragma unroll
    for (int i = 0; i < 8; i++) { bestd[i] = 3.4e38f; bestk[i] = 0; }

    for (int kt = 0; kt < KCODE / TN; kt++) {
        int k0 = kt * TN;
        float acc[8][8];
#pragma unroll
        for (int i = 0; i < 8; i++)
#pragma unroll
            for (int j = 0; j < 8; j++) acc[i][j] = 0.f;

        for (int cch = 0; cch < 4; cch++) {
            __syncthreads();
            {   // load codebook chunk: rows k0..k0+127, features cch*64..+63
                int kk = tid >> 1, half = tid & 1;
                const float* rowp = cb + (size_t)(k0 + kk) * CDIM + cch * 64 + half * 32;
#pragma unroll
                for (int q = 0; q < 8; q++) {
                    float4 v = *(const float4*)(rowp + q * 4);
                    int cb0 = half * 32 + q * 4;
                    es[(cb0 + 0) * ES_STR + kk] = v.x;
                    es[(cb0 + 1) * ES_STR + kk] = v.y;
                    es[(cb0 + 2) * ES_STR + kk] = v.z;
                    es[(cb0 + 3) * ES_STR + kk] = v.w;
                }
            }
            __syncthreads();

#pragma unroll 4
            for (int cp = 0; cp < 64; cp++) {
                const float* xr = xs + (cch * 64 + cp) * 128 + ty * 8;
                float4 xa = *(const float4*)(xr);
                float4 xb = *(const float4*)(xr + 4);
                const float* er = es + cp * ES_STR + tx * 8;
                float4 ea = *(const float4*)(er);
                float4 eb = *(const float4*)(er + 4);
                float xv[8] = {xa.x, xa.y, xa.z, xa.w, xb.x, xb.y, xb.z, xb.w};
                float ev[8] = {ea.x, ea.y, ea.z, ea.w, eb.x, eb.y, eb.z, eb.w};
#pragma unroll
                for (int i = 0; i < 8; i++)
#pragma unroll
                    for (int j = 0; j < 8; j++)
                        acc[i][j] += xv[i] * ev[j];          // FFMA, fixed c-order
            }
        }

        // Epilogue: emulate reference fp32 rounding:
        //   d = fl( fl(sx2 + se2_k) - 2*dot_k ), argmin with ties -> lowest k
        float se2v[8];
#pragma unroll
        for (int j = 0; j < 8; j++) se2v[j] = g_se2[k0 + tx * 8 + j];
#pragma unroll
        for (int i = 0; i < 8; i++) {
            float di = 3.4e38f; int ki = 0x7fffffff;
#pragma unroll
            for (int j = 0; j < 8; j++) {                      // ascending k
                float t3 = __fadd_rn(sx2v[i], se2v[j]);
                float dv = __fsub_rn(t3, 2.0f * acc[i][j]);
                if (dv < di) { di = dv; ki = k0 + tx * 8 + j; }
            }
            // reduce across the 16 tx lanes of this row (within warp half)
#pragma unroll
            for (int o = 1; o < 16; o <<= 1) {
                float od = __shfl_xor_sync(0xffffffffu, di, o);
                int   ok = __shfl_xor_sync(0xffffffffu, ki, o);
                if (od < di || (od == di && ok < ki)) { di = od; ki = ok; }
            }
            if (di < bestd[i]) { bestd[i] = di; bestk[i] = ki; }  // ties keep lower kt
        }
    }

    if (tx == 0) {
#pragma unroll
        for (int i = 0; i < 8; i++) {
            int n = m0 + ty * 8 + i;
            int k = bestk[i];
            g_idx[n] = k;
            out[IDX_OFF + n] = (float)k;
            out[OH_OFF + (size_t)n * KCODE + k] = 1.0f;
            atomicAdd(&g_hist[k], 1);
        }
    }
}

// ---------------------------------------------------------------------------
// x_quantized (with STE rounding emulated) + loss partial sums.
__global__ void k_xq(const float* __restrict__ x, const float* __restrict__ cb,
                     float* __restrict__ out) {
    int e = blockIdx.x * blockDim.x + threadIdx.x;   // < 8388608
    int b = e >> 18;
    int rem = e & 262143;
    int c = rem >> 10;
    int hw = rem & 1023;
    int n = (b << 10) + hw;
    int k = g_idx[n];
    float ev = cb[(size_t)k * CDIM + c];
    float xv = x[e];
    // straight-through: xt + fl(xq - xt), matching reference fp32 rounding
    out[XQ_OFF + e] = __fadd_rn(xv, __fsub_rn(ev, xv));

    float d1 = xv - ev;
    double s1 = (double)d1, s2 = (double)d1 * (double)d1;
#pragma unroll
    for (int o = 16; o > 0; o >>= 1) {
        s1 += __shfl_down_sync(0xffffffffu, s1, o);
        s2 += __shfl_down_sync(0xffffffffu, s2, o);
    }
    __shared__ double sh[64];
    int lane = threadIdx.x & 31, w = threadIdx.x >> 5;
    if (lane == 0) { sh[w] = s1; sh[w + 32] = s2; }
    __syncthreads();
    if (w == 0) {
        double a = sh[lane], bq = sh[lane + 32];
#pragma unroll
        for (int o = 16; o > 0; o >>= 1) {
            a  += __shfl_down_sync(0xffffffffu, a, o);
            bq += __shfl_down_sync(0xffffffffu, bq, o);
        }
        if (lane == 0) { g_part[2 * blockIdx.x] = a; g_part[2 * blockIdx.x + 1] = bq; }
    }
}

// ---------------------------------------------------------------------------
// Final scalars: loss + perplexity (deterministic fixed-tree reductions).
__global__ void k_final(float* __restrict__ out) {
    __shared__ double sa[256], sb[256], shh[256];
    int t = threadIdx.x;
    double a = 0.0, b = 0.0;
    for (int i = t; i < 8192; i += 256) { a += g_part[2 * i]; b += g_part[2 * i + 1]; }
    sa[t] = a; sb[t] = b;
    double h = 0.0;
    for (int i = t; i < KCODE; i += 256) {
        float p = (float)g_hist[i] * (1.0f / 32768.0f);
        h += (double)(p * logf(p + 1e-10f));
    }
    shh[t] = h;
    __syncthreads();
    for (int s = 128; s > 0; s >>= 1) {
        if (t < s) { sa[t] += sa[t + s]; sb[t] += sb[t + s]; shh[t] += shh[t + s]; }
        __syncthreads();
    }
    if (t == 0) {
        double loss = 0.25 * (sa[0] / (double)NE) + sb[0] / (double)NE;
        out[LOSS_OFF] = (float)loss;
        out[PERP_OFF] = (float)exp(-shh[0]);
    }
}

// ---------------------------------------------------------------------------
extern "C" void kernel_launch(void* const* d_in, const int* in_sizes, int n_in,
                              void* d_out, int out_size) {
    const float* x  = (const float*)d_in[0];   // [32,256,32,32]
    const float* cb = (const float*)d_in[1];   // [8192,256]
    float* out = (float*)d_out;

    // zero the one-hot region (poisoned to 0xAA by the harness)
    cudaMemsetAsync(out + OH_OFF, 0, (size_t)N_TOK * KCODE * sizeof(float));

    k_init<<<1, 256>>>();
    k_se2<<<KCODE / 8, 256>>>(cb);      // 8 warps/block, one warp per code
    k_sx2<<<N_TOK / 256, 256>>>(x);

    cudaFuncSetAttribute(k_main, cudaFuncAttributeMaxDynamicSharedMemorySize,
                         SMEM_MAIN);
    k_main<<<N_TOK / TM, 256, SMEM_MAIN>>>(x, cb, out);

    k_xq<<<NE / 1024, 1024>>>(x, cb, out);
    k_final<<<1, 256>>>(out);
}

// round 3
// speedup vs baseline: 1.0287x; 1.0287x over previous
#include <cuda_runtime.h>
#include <cstdint>
#include <cstdio>

// Problem constants
#define N_TOK 32768      // tokens = 32 * 32 * 32
#define KCODE 8192       // codebook size
#define CDIM  256        // token size
#define NE    8388608    // total elements of x (32*256*32*32)

// Output layout (concatenated, all float32):
// x_quantized [8388608], loss [1], perplexity [1],
// min_encodings [32768*8192], min_encoding_indices [32768]
#define XQ_OFF   0
#define LOSS_OFF 8388608ULL
#define PERP_OFF 8388609ULL
#define OH_OFF   8388610ULL
#define IDX_OFF  276824066ULL

// Scratch (no device allocation allowed -> __device__ globals)
__device__ float  g_se2[KCODE];     // sum_c e^2 per code (fp32, like jnp.sum)
__device__ float  g_sx2[N_TOK];     // sum_c x^2 per token (fp32)
__device__ int    g_idx[N_TOK];     // argmin index per token
__device__ int    g_hist[KCODE];    // histogram of selected codes
__device__ double g_part[8192 * 2]; // per-block loss partials (sum diff, sum diff^2)

// ---------------------------------------------------------------------------
__global__ void k_init() {
    int t = threadIdx.x;
    for (int i = t; i < KCODE; i += blockDim.x) g_hist[i] = 0;
}

// sum of squares per codebook row: one warp per code
__global__ void k_se2(const float* __restrict__ cb) {
    int gw = (blockIdx.x * blockDim.x + threadIdx.x) >> 5;  // global warp = code
    int lane = threadIdx.x & 31;
    if (gw >= KCODE) return;
    const float* row = cb + (size_t)gw * CDIM;
    float s = 0.f;
#pragma unroll
    for (int w = 0; w < 8; w++) { float v = row[lane + w * 32]; s += v * v; }
#pragma unroll
    for (int o = 16; o > 0; o >>= 1) s += __shfl_down_sync(0xffffffffu, s, o);
    if (lane == 0) g_se2[gw] = s;
}

// sum of squares per token (x layout [B,C,H,W]; token n = b*1024 + hw)
__global__ void k_sx2(const float* __restrict__ x) {
    int n = blockIdx.x * blockDim.x + threadIdx.x;
    if (n >= N_TOK) return;
    int b = n >> 10, hw = n & 1023;
    const float* px = x + (size_t)b * 262144 + hw;
    float s = 0.f;
#pragma unroll 8
    for (int c = 0; c < CDIM; c++) { float v = px[c * 1024]; s += v * v; }
    g_sx2[n] = s;
}

// ---------------------------------------------------------------------------
// Main distance GEMM + argmin. Tile: 128 tokens x 128 codes per CTA,
// 256 threads, 8x8 micro-tiles via packed f32x2 FMA (fma.rn.f32x2).
// Full x tile in smem (128 KB); codebook streamed in 64-c chunks,
// DOUBLE-BUFFERED (2 x 33 KB) with global prefetch into registers.
#define TM 128
#define TN 128
#define ES_STR 132                       // 128 + 4 pad floats per c-row
#define ES_BUF (64 * ES_STR)             // one chunk buffer (floats)
#define SMEM_MAIN (256 * 128 * 4 + 2 * ES_BUF * 4)   // 131072 + 67584 = 198656

extern __shared__ float smem[];

__device__ __forceinline__ void fma2(unsigned long long& acc,
                                     unsigned long long a,
                                     unsigned long long b) {
    asm("fma.rn.f32x2 %0, %1, %2, %0;" : "+l"(acc) : "l"(a), "l"(b));
}
__device__ __forceinline__ unsigned long long dup2(unsigned int v) {
    unsigned long long r;
    asm("mov.b64 %0, {%1, %1};" : "=l"(r) : "r"(v));
    return r;
}

__global__ __launch_bounds__(256, 1)
void k_main(const float* __restrict__ x, const float* __restrict__ cb,
            float* __restrict__ out) {
    float* xs = smem;               // [256][128] : xs[c][m]
    float* es = smem + 256 * 128;   // 2 buffers of [64][ES_STR] : es[c'][kk]

    int tid = threadIdx.x;
    int tx = tid & 15, ty = tid >> 4;
    int m0 = blockIdx.x * TM;                    // 1024 % 128 == 0 -> single b
    int bb = m0 >> 10, hw0 = m0 & 1023;
    const float* px = x + (size_t)bb * 262144 + hw0;

    // Load x tile into smem, transposed to [c][m]; coalesced float4 loads.
#pragma unroll 4
    for (int i = 0; i < 32; i++) {
        int idx4 = tid + i * 256;                // 0..8191 float4s
        int c = idx4 >> 5, m4 = (idx4 & 31) * 4;
        float4 v = *(const float4*)(px + c * 1024 + m4);
        *(float4*)(xs + c * 128 + m4) = v;
    }

    // codebook chunk loader: chunk q covers codes [ (q>>2)*128 ) and
    // features [ (q&3)*64 ). Per thread: 8 float4 prefetch registers.
    int kk = tid >> 1, half = tid & 1;
    float4 pf[8];
    {   // prologue: chunk 0
        const float4* rowp = (const float4*)(cb + (size_t)kk * CDIM + half * 32);
#pragma unroll
        for (int q4 = 0; q4 < 8; q4++) pf[q4] = rowp[q4];
        float* dst = es;                         // buffer 0
#pragma unroll
        for (int q4 = 0; q4 < 8; q4++) {
            int cb0 = half * 32 + q4 * 4;
            dst[(cb0 + 0) * ES_STR + kk] = pf[q4].x;
            dst[(cb0 + 1) * ES_STR + kk] = pf[q4].y;
            dst[(cb0 + 2) * ES_STR + kk] = pf[q4].z;
            dst[(cb0 + 3) * ES_STR + kk] = pf[q4].w;
        }
    }
    __syncthreads();

    float sx2v[8];
#pragma unroll
    for (int i = 0; i < 8; i++) sx2v[i] = g_sx2[m0 + ty * 8 + i];

    float bestd[8]; int bestk[8];
#pragma unroll
    for (int i = 0; i < 8; i++) { bestd[i] = 3.4e38f; bestk[i] = 0; }

    for (int kt = 0; kt < KCODE / TN; kt++) {
        int k0 = kt * TN;
        unsigned long long acc[8][4];            // [i][j-pair], lo=j even
#pragma unroll
        for (int i = 0; i < 8; i++)
#pragma unroll
            for (int p = 0; p < 4; p++) acc[i][p] = 0ull;

        for (int cch = 0; cch < 4; cch++) {
            int q = kt * 4 + cch;                // current chunk id
            if (q < 255) {                       // prefetch next chunk
                int qn = q + 1;
                int nk0 = (qn >> 2) << 7, nc0 = (qn & 3) << 6;
                const float4* rowp = (const float4*)(cb + (size_t)(nk0 + kk) * CDIM
                                                     + nc0 + half * 32);
#pragma unroll
                for (int q4 = 0; q4 < 8; q4++) pf[q4] = rowp[q4];
            }

            const float* eb = es + (q & 1) * ES_BUF;
#pragma unroll 4
            for (int cp = 0; cp < 64; cp++) {
                const unsigned int* xr =
                    (const unsigned int*)(xs + (cch * 64 + cp) * 128 + ty * 8);
                uint4 xa = *(const uint4*)(xr);
                uint4 xb = *(const uint4*)(xr + 4);
                const unsigned long long* er =
                    (const unsigned long long*)(eb + cp * ES_STR + tx * 8);
                unsigned long long e0 = er[0], e1 = er[1], e2 = er[2], e3 = er[3];
                unsigned long long xd[8] = {
                    dup2(xa.x), dup2(xa.y), dup2(xa.z), dup2(xa.w),
                    dup2(xb.x), dup2(xb.y), dup2(xb.z), dup2(xb.w)};
#pragma unroll
                for (int i = 0; i < 8; i++) {
                    fma2(acc[i][0], xd[i], e0);
                    fma2(acc[i][1], xd[i], e1);
                    fma2(acc[i][2], xd[i], e2);
                    fma2(acc[i][3], xd[i], e3);
                }
            }

            if (q < 255) {                       // store prefetched chunk
                float* dst = es + ((q + 1) & 1) * ES_BUF;
#pragma unroll
                for (int q4 = 0; q4 < 8; q4++) {
                    int cb0 = half * 32 + q4 * 4;
                    dst[(cb0 + 0) * ES_STR + kk] = pf[q4].x;
                    dst[(cb0 + 1) * ES_STR + kk] = pf[q4].y;
                    dst[(cb0 + 2) * ES_STR + kk] = pf[q4].z;
                    dst[(cb0 + 3) * ES_STR + kk] = pf[q4].w;
                }
                __syncthreads();
            }
        }

        // Epilogue: emulate reference fp32 rounding:
        //   d = fl( fl(sx2 + se2_k) - 2*dot_k ), argmin with ties -> lowest k
        float se2v[8];
#pragma unroll
        for (int j = 0; j < 8; j++) se2v[j] = g_se2[k0 + tx * 8 + j];
#pragma unroll
        for (int i = 0; i < 8; i++) {
            float di = 3.4e38f; int ki = 0x7fffffff;
#pragma unroll
            for (int p = 0; p < 4; p++) {                      // ascending j
                float dlo = __uint_as_float((unsigned int)acc[i][p]);
                float dhi = __uint_as_float((unsigned int)(acc[i][p] >> 32));
                int j0 = 2 * p;
                float t3 = __fadd_rn(sx2v[i], se2v[j0]);
                float dv = __fsub_rn(t3, 2.0f * dlo);
                if (dv < di) { di = dv; ki = k0 + tx * 8 + j0; }
                t3 = __fadd_rn(sx2v[i], se2v[j0 + 1]);
                dv = __fsub_rn(t3, 2.0f * dhi);
                if (dv < di) { di = dv; ki = k0 + tx * 8 + j0 + 1; }
            }
            // reduce across the 16 tx lanes of this row (within warp half)
#pragma unroll
            for (int o = 1; o < 16; o <<= 1) {
                float od = __shfl_xor_sync(0xffffffffu, di, o);
                int   ok = __shfl_xor_sync(0xffffffffu, ki, o);
                if (od < di || (od == di && ok < ki)) { di = od; ki = ok; }
            }
            if (di < bestd[i]) { bestd[i] = di; bestk[i] = ki; }  // ties keep lower kt
        }
    }

    if (tx == 0) {
#pragma unroll
        for (int i = 0; i < 8; i++) {
            int n = m0 + ty * 8 + i;
            int k = bestk[i];
            g_idx[n] = k;
            out[IDX_OFF + n] = (float)k;
            out[OH_OFF + (size_t)n * KCODE + k] = 1.0f;
            atomicAdd(&g_hist[k], 1);
        }
    }
}

// ---------------------------------------------------------------------------
// x_quantized (with STE rounding emulated) + loss partial sums.
__global__ void k_xq(const float* __restrict__ x, const float* __restrict__ cb,
                     float* __restrict__ out) {
    int e = blockIdx.x * blockDim.x + threadIdx.x;   // < 8388608
    int b = e >> 18;
    int rem = e & 262143;
    int c = rem >> 10;
    int hw = rem & 1023;
    int n = (b << 10) + hw;
    int k = g_idx[n];
    float ev = cb[(size_t)k * CDIM + c];
    float xv = x[e];
    // straight-through: xt + fl(xq - xt), matching reference fp32 rounding
    out[XQ_OFF + e] = __fadd_rn(xv, __fsub_rn(ev, xv));

    float d1 = xv - ev;
    double s1 = (double)d1, s2 = (double)d1 * (double)d1;
#pragma unroll
    for (int o = 16; o > 0; o >>= 1) {
        s1 += __shfl_down_sync(0xffffffffu, s1, o);
        s2 += __shfl_down_sync(0xffffffffu, s2, o);
    }
    __shared__ double sh[64];
    int lane = threadIdx.x & 31, w = threadIdx.x >> 5;
    if (lane == 0) { sh[w] = s1; sh[w + 32] = s2; }
    __syncthreads();
    if (w == 0) {
        double a = sh[lane], bq = sh[lane + 32];
#pragma unroll
        for (int o = 16; o > 0; o >>= 1) {
            a  += __shfl_down_sync(0xffffffffu, a, o);
            bq += __shfl_down_sync(0xffffffffu, bq, o);
        }
        if (lane == 0) { g_part[2 * blockIdx.x] = a; g_part[2 * blockIdx.x + 1] = bq; }
    }
}

// ---------------------------------------------------------------------------
// Final scalars: loss + perplexity (deterministic fixed-tree reductions).
__global__ void k_final(float* __restrict__ out) {
    __shared__ double sa[256], sb[256], shh[256];
    int t = threadIdx.x;
    double a = 0.0, b = 0.0;
    for (int i = t; i < 8192; i += 256) { a += g_part[2 * i]; b += g_part[2 * i + 1]; }
    sa[t] = a; sb[t] = b;
    double h = 0.0;
    for (int i = t; i < KCODE; i += 256) {
        float p = (float)g_hist[i] * (1.0f / 32768.0f);
        h += (double)(p * logf(p + 1e-10f));
    }
    shh[t] = h;
    __syncthreads();
    for (int s = 128; s > 0; s >>= 1) {
        if (t < s) { sa[t] += sa[t + s]; sb[t] += sb[t + s]; shh[t] += shh[t + s]; }
        __syncthreads();
    }
    if (t == 0) {
        double loss = 0.25 * (sa[0] / (double)NE) + sb[0] / (double)NE;
        out[LOSS_OFF] = (float)loss;
        out[PERP_OFF] = (float)exp(-shh[0]);
    }
}

// ---------------------------------------------------------------------------
extern "C" void kernel_launch(void* const* d_in, const int* in_sizes, int n_in,
                              void* d_out, int out_size) {
    const float* x  = (const float*)d_in[0];   // [32,256,32,32]
    const float* cb = (const float*)d_in[1];   // [8192,256]
    float* out = (float*)d_out;

    // zero the one-hot region (poisoned to 0xAA by the harness)
    cudaMemsetAsync(out + OH_OFF, 0, (size_t)N_TOK * KCODE * sizeof(float));

    k_init<<<1, 256>>>();
    k_se2<<<KCODE / 8, 256>>>(cb);      // 8 warps/block, one warp per code
    k_sx2<<<N_TOK / 256, 256>>>(x);

    cudaFuncSetAttribute(k_main, cudaFuncAttributeMaxDynamicSharedMemorySize,
                         SMEM_MAIN);
    k_main<<<N_TOK / TM, 256, SMEM_MAIN>>>(x, cb, out);

    k_xq<<<NE / 1024, 1024>>>(x, cb, out);
    k_final<<<1, 256>>>(out);
}

// round 9
// speedup vs baseline: 1.1208x; 1.0895x over previous
#include <cuda_runtime.h>
#include <cstdint>
#include <cstdio>

// Problem constants
#define N_TOK 32768      // tokens = 32 * 32 * 32
#define KCODE 8192       // codebook size
#define CDIM  256        // token size
#define NE    8388608    // total elements of x (32*256*32*32)

// Output layout (concatenated, all float32):
// x_quantized [8388608], loss [1], perplexity [1],
// min_encodings [32768*8192], min_encoding_indices [32768]
#define XQ_OFF   0
#define LOSS_OFF 8388608ULL
#define PERP_OFF 8388609ULL
#define OH_OFF   8388610ULL
#define IDX_OFF  276824066ULL

// Scratch (no device allocation allowed -> __device__ globals)
__device__ float  g_se2[KCODE];     // sum_c e^2 per code (fp32, like jnp.sum)
__device__ float  g_sx2[N_TOK];     // sum_c x^2 per token (fp32)
__device__ int    g_idx[N_TOK];     // argmin index per token
__device__ int    g_hist[KCODE];    // histogram of selected codes
__device__ double g_part[8192 * 2]; // per-block loss partials (sum diff, sum diff^2)

// ---------------------------------------------------------------------------
__global__ void k_init() {
    int t = threadIdx.x;
    for (int i = t; i < KCODE; i += blockDim.x) g_hist[i] = 0;
}

// sum of squares per codebook row: one warp per code
__global__ void k_se2(const float* __restrict__ cb) {
    int gw = (blockIdx.x * blockDim.x + threadIdx.x) >> 5;  // global warp = code
    int lane = threadIdx.x & 31;
    if (gw >= KCODE) return;
    const float* row = cb + (size_t)gw * CDIM;
    float s = 0.f;
#pragma unroll
    for (int w = 0; w < 8; w++) { float v = row[lane + w * 32]; s += v * v; }
#pragma unroll
    for (int o = 16; o > 0; o >>= 1) s += __shfl_down_sync(0xffffffffu, s, o);
    if (lane == 0) g_se2[gw] = s;
}

// sum of squares per token (x layout [B,C,H,W]; token n = b*1024 + hw)
__global__ void k_sx2(const float* __restrict__ x) {
    int n = blockIdx.x * blockDim.x + threadIdx.x;
    if (n >= N_TOK) return;
    int b = n >> 10, hw = n & 1023;
    const float* px = x + (size_t)b * 262144 + hw;
    float s = 0.f;
#pragma unroll 8
    for (int c = 0; c < CDIM; c++) { float v = px[c * 1024]; s += v * v; }
    g_sx2[n] = s;
}

// ---------------------------------------------------------------------------
// Main distance GEMM + argmin. Tile: 128 tokens x 128 codes per CTA,
// 512 threads. Warp = fixed ty (8 token rows); tx in 0..31 owns codes
// j = tx*4..tx*4+3 (one conflict-free LDS.128 per cp). Accumulators are
// packed f32x2 pairs ALONG TOKENS (i), so x loads straight from smem as
// u64 pairs -- no duplication movs; only e gets dup'd (4 per cp).
// Full x tile in smem (128 KB); codebook streamed in 64-c chunks,
// double-buffered with global->register prefetch.
#define TM 128
#define TN 128
#define ES_STR 132                       // 128 + 4 pad floats per c-row
#define ES_BUF (64 * ES_STR)             // one chunk buffer (floats)
#define SMEM_MAIN (256 * 128 * 4 + 2 * ES_BUF * 4)   // 131072 + 67584 = 198656

extern __shared__ float smem[];

typedef unsigned long long u64;

__device__ __forceinline__ void fma2(u64& acc, u64 a, u64 b) {
    asm("fma.rn.f32x2 %0, %1, %2, %0;" : "+l"(acc) : "l"(a), "l"(b));
}
__device__ __forceinline__ u64 dup2(float v) {
    u64 r;
    asm("mov.b64 %0, {%1, %1};" : "=l"(r) : "f"(v));
    return r;
}
__device__ __forceinline__ float f2lo(u64 v) {
    return __uint_as_float((unsigned int)v);
}
__device__ __forceinline__ float f2hi(u64 v) {
    return __uint_as_float((unsigned int)(v >> 32));
}

__global__ __launch_bounds__(512, 1)
void k_main(const float* __restrict__ x, const float* __restrict__ cb,
            float* __restrict__ out) {
    float* xs = smem;               // [256][128] : xs[c][m]
    float* es = smem + 256 * 128;   // 2 buffers of [64][ES_STR] : es[c'][kk]

    int tid = threadIdx.x;
    int tx = tid & 31;              // code group: j = tx*4 .. tx*4+3
    int ty = tid >> 5;              // warp id = token group: i = ty*8 .. ty*8+7
    int m0 = blockIdx.x * TM;       // 1024 % 128 == 0 -> single batch b
    int bb = m0 >> 10, hw0 = m0 & 1023;
    const float* px = x + (size_t)bb * 262144 + hw0;

    // Load x tile into smem, transposed to [c][m]; coalesced float4 loads.
#pragma unroll 4
    for (int i = 0; i < 16; i++) {
        int idx4 = tid + i * 512;                // 0..8191 float4s
        int c = idx4 >> 5, m4 = (idx4 & 31) * 4;
        float4 v = *(const float4*)(px + c * 1024 + m4);
        *(float4*)(xs + c * 128 + m4) = v;
    }

    // Codebook chunk loader: chunk q covers codes [(q>>2)*128) and features
    // [(q&3)*64). 512 threads: kk = tid>>2 (code row), seg = tid&3 (16 floats).
    int kk = tid >> 2, seg = tid & 3;
    float4 pf[4];
    {   // prologue: chunk 0
        const float4* rowp = (const float4*)(cb + (size_t)kk * CDIM + seg * 16);
#pragma unroll
        for (int q4 = 0; q4 < 4; q4++) pf[q4] = rowp[q4];
        float* dst = es;                         // buffer 0
#pragma unroll
        for (int q4 = 0; q4 < 4; q4++) {
            int c0 = seg * 16 + q4 * 4;
            dst[(c0 + 0) * ES_STR + kk] = pf[q4].x;
            dst[(c0 + 1) * ES_STR + kk] = pf[q4].y;
            dst[(c0 + 2) * ES_STR + kk] = pf[q4].z;
            dst[(c0 + 3) * ES_STR + kk] = pf[q4].w;
        }
    }
    __syncthreads();

    float sx2v[8];
#pragma unroll
    for (int i = 0; i < 8; i++) sx2v[i] = g_sx2[m0 + ty * 8 + i];

    float bestd[8]; int bestk[8];
#pragma unroll
    for (int i = 0; i < 8; i++) { bestd[i] = 3.4e38f; bestk[i] = 0; }

    for (int kt = 0; kt < KCODE / TN; kt++) {
        int k0 = kt * TN;
        u64 acc[4][4];                  // [i-pair][j], lo = i even
#pragma unroll
        for (int p = 0; p < 4; p++)
#pragma unroll
            for (int j = 0; j < 4; j++) acc[p][j] = 0ull;

        for (int cch = 0; cch < 4; cch++) {
            int q = kt * 4 + cch;                // current chunk id
            if (q < 255) {                       // prefetch next chunk
                int qn = q + 1;
                int nk0 = (qn >> 2) << 7, nc0 = (qn & 3) << 6;
                const float4* rowp = (const float4*)(cb + (size_t)(nk0 + kk) * CDIM
                                                     + nc0 + seg * 16);
#pragma unroll
                for (int q4 = 0; q4 < 4; q4++) pf[q4] = rowp[q4];
            }

            const float* eb = es + (q & 1) * ES_BUF;
#pragma unroll 4
            for (int cp = 0; cp < 64; cp++) {
                const u64* xr = (const u64*)(xs + (cch * 64 + cp) * 128 + ty * 8);
                u64 x0 = xr[0], x1 = xr[1], x2 = xr[2], x3 = xr[3];
                float4 ev = *(const float4*)(eb + cp * ES_STR + tx * 4);
                u64 e0 = dup2(ev.x), e1 = dup2(ev.y),
                    e2 = dup2(ev.z), e3 = dup2(ev.w);
                fma2(acc[0][0], x0, e0); fma2(acc[0][1], x0, e1);
                fma2(acc[0][2], x0, e2); fma2(acc[0][3], x0, e3);
                fma2(acc[1][0], x1, e0); fma2(acc[1][1], x1, e1);
                fma2(acc[1][2], x1, e2); fma2(acc[1][3], x1, e3);
                fma2(acc[2][0], x2, e0); fma2(acc[2][1], x2, e1);
                fma2(acc[2][2], x2, e2); fma2(acc[2][3], x2, e3);
                fma2(acc[3][0], x3, e0); fma2(acc[3][1], x3, e1);
                fma2(acc[3][2], x3, e2); fma2(acc[3][3], x3, e3);
            }

            if (q < 255) {                       // store prefetched chunk
                float* dst = es + ((q + 1) & 1) * ES_BUF;
#pragma unroll
                for (int q4 = 0; q4 < 4; q4++) {
                    int c0 = seg * 16 + q4 * 4;
                    dst[(c0 + 0) * ES_STR + kk] = pf[q4].x;
                    dst[(c0 + 1) * ES_STR + kk] = pf[q4].y;
                    dst[(c0 + 2) * ES_STR + kk] = pf[q4].z;
                    dst[(c0 + 3) * ES_STR + kk] = pf[q4].w;
                }
                __syncthreads();
            }
        }

        // Epilogue: emulate reference fp32 rounding:
        //   d = fl( fl(sx2 + se2_k) - 2*dot_k ), argmin with ties -> lowest k
        float se2v[4];
#pragma unroll
        for (int j = 0; j < 4; j++) se2v[j] = g_se2[k0 + tx * 4 + j];
#pragma unroll
        for (int p = 0; p < 4; p++) {
#pragma unroll
            for (int h = 0; h < 2; h++) {
                int i = 2 * p + h;
                float di = 3.4e38f; int ki = 0x7fffffff;
#pragma unroll
                for (int j = 0; j < 4; j++) {                  // ascending j
                    float dot = h ? f2hi(acc[p][j]) : f2lo(acc[p][j]);
                    float t3 = __fadd_rn(sx2v[i], se2v[j]);
                    float dv = __fsub_rn(t3, 2.0f * dot);
                    if (dv < di) { di = dv; ki = k0 + tx * 4 + j; }
                }
                // reduce across all 32 lanes (tx spans full code tile)
#pragma unroll
                for (int o = 1; o < 32; o <<= 1) {
                    float od = __shfl_xor_sync(0xffffffffu, di, o);
                    int   ok = __shfl_xor_sync(0xffffffffu, ki, o);
                    if (od < di || (od == di && ok < ki)) { di = od; ki = ok; }
                }
                if (di < bestd[i]) { bestd[i] = di; bestk[i] = ki; }
            }
        }
    }

    if (tx == 0) {
#pragma unroll
        for (int i = 0; i < 8; i++) {
            int n = m0 + ty * 8 + i;
            int k = bestk[i];
            g_idx[n] = k;
            out[IDX_OFF + n] = (float)k;
            out[OH_OFF + (size_t)n * KCODE + k] = 1.0f;
            atomicAdd(&g_hist[k], 1);
        }
    }
}

// ---------------------------------------------------------------------------
// x_quantized (with STE rounding emulated) + loss partial sums.
__global__ void k_xq(const float* __restrict__ x, const float* __restrict__ cb,
                     float* __restrict__ out) {
    int e = blockIdx.x * blockDim.x + threadIdx.x;   // < 8388608
    int b = e >> 18;
    int rem = e & 262143;
    int c = rem >> 10;
    int hw = rem & 1023;
    int n = (b << 10) + hw;
    int k = g_idx[n];
    float ev = cb[(size_t)k * CDIM + c];
    float xv = x[e];
    // straight-through: xt + fl(xq - xt), matching reference fp32 rounding
    out[XQ_OFF + e] = __fadd_rn(xv, __fsub_rn(ev, xv));

    float d1 = xv - ev;
    double s1 = (double)d1, s2 = (double)d1 * (double)d1;
#pragma unroll
    for (int o = 16; o > 0; o >>= 1) {
        s1 += __shfl_down_sync(0xffffffffu, s1, o);
        s2 += __shfl_down_sync(0xffffffffu, s2, o);
    }
    __shared__ double sh[64];
    int lane = threadIdx.x & 31, w = threadIdx.x >> 5;
    if (lane == 0) { sh[w] = s1; sh[w + 32] = s2; }
    __syncthreads();
    if (w == 0) {
        double a = sh[lane], bq = sh[lane + 32];
#pragma unroll
        for (int o = 16; o > 0; o >>= 1) {
            a  += __shfl_down_sync(0xffffffffu, a, o);
            bq += __shfl_down_sync(0xffffffffu, bq, o);
        }
        if (lane == 0) { g_part[2 * blockIdx.x] = a; g_part[2 * blockIdx.x + 1] = bq; }
    }
}

// ---------------------------------------------------------------------------
// Final scalars: loss + perplexity (deterministic fixed-tree reductions).
__global__ void k_final(float* __restrict__ out) {
    __shared__ double sa[256], sb[256], shh[256];
    int t = threadIdx.x;
    double a = 0.0, b = 0.0;
    for (int i = t; i < 8192; i += 256) { a += g_part[2 * i]; b += g_part[2 * i + 1]; }
    sa[t] = a; sb[t] = b;
    double h = 0.0;
    for (int i = t; i < KCODE; i += 256) {
        float p = (float)g_hist[i] * (1.0f / 32768.0f);
        h += (double)(p * logf(p + 1e-10f));
    }
    shh[t] = h;
    __syncthreads();
    for (int s = 128; s > 0; s >>= 1) {
        if (t < s) { sa[t] += sa[t + s]; sb[t] += sb[t + s]; shh[t] += shh[t + s]; }
        __syncthreads();
    }
    if (t == 0) {
        double loss = 0.25 * (sa[0] / (double)NE) + sb[0] / (double)NE;
        out[LOSS_OFF] = (float)loss;
        out[PERP_OFF] = (float)exp(-shh[0]);
    }
}

// ---------------------------------------------------------------------------
extern "C" void kernel_launch(void* const* d_in, const int* in_sizes, int n_in,
                              void* d_out, int out_size) {
    const float* x  = (const float*)d_in[0];   // [32,256,32,32]
    const float* cb = (const float*)d_in[1];   // [8192,256]
    float* out = (float*)d_out;

    // zero the one-hot region (poisoned to 0xAA by the harness)
    cudaMemsetAsync(out + OH_OFF, 0, (size_t)N_TOK * KCODE * sizeof(float));

    k_init<<<1, 256>>>();
    k_se2<<<KCODE / 8, 256>>>(cb);      // 8 warps/block, one warp per code
    k_sx2<<<N_TOK / 256, 256>>>(x);

    cudaFuncSetAttribute(k_main, cudaFuncAttributeMaxDynamicSharedMemorySize,
                         SMEM_MAIN);
    k_main<<<N_TOK / TM, 512, SMEM_MAIN>>>(x, cb, out);

    k_xq<<<NE / 1024, 1024>>>(x, cb, out);
    k_final<<<1, 256>>>(out);
}

// round 13
// speedup vs baseline: 1.1526x; 1.0284x over previous
#include <cuda_runtime.h>
#include <cstdint>
#include <cstdio>

// Problem constants
#define N_TOK 32768      // tokens = 32 * 32 * 32
#define KCODE 8192       // codebook size
#define CDIM  256        // token size
#define NE    8388608    // total elements of x (32*256*32*32)

// Output layout (concatenated, all float32):
// x_quantized [8388608], loss [1], perplexity [1],
// min_encodings [32768*8192], min_encoding_indices [32768]
#define XQ_OFF   0
#define LOSS_OFF 8388608ULL
#define PERP_OFF 8388609ULL
#define OH_OFF   8388610ULL
#define IDX_OFF  276824066ULL

// Scratch (no device allocation allowed -> __device__ globals)
__device__ float  g_se2[KCODE];     // sum_c e^2 per code (fp32, like jnp.sum)
__device__ float  g_sx2[N_TOK];     // sum_c x^2 per token (fp32)
__device__ int    g_idx[N_TOK];     // argmin index per token
__device__ int    g_hist[KCODE];    // histogram of selected codes
__device__ double g_part[8192 * 2]; // per-block loss partials (sum diff, sum diff^2)

// ---------------------------------------------------------------------------
__global__ void k_init() {
    int t = threadIdx.x;
    for (int i = t; i < KCODE; i += blockDim.x) g_hist[i] = 0;
}

// sum of squares per codebook row: one warp per code
__global__ void k_se2(const float* __restrict__ cb) {
    int gw = (blockIdx.x * blockDim.x + threadIdx.x) >> 5;  // global warp = code
    int lane = threadIdx.x & 31;
    if (gw >= KCODE) return;
    const float* row = cb + (size_t)gw * CDIM;
    float s = 0.f;
#pragma unroll
    for (int w = 0; w < 8; w++) { float v = row[lane + w * 32]; s += v * v; }
#pragma unroll
    for (int o = 16; o > 0; o >>= 1) s += __shfl_down_sync(0xffffffffu, s, o);
    if (lane == 0) g_se2[gw] = s;
}

// sum of squares per token (x layout [B,C,H,W]; token n = b*1024 + hw)
__global__ void k_sx2(const float* __restrict__ x) {
    int n = blockIdx.x * blockDim.x + threadIdx.x;
    if (n >= N_TOK) return;
    int b = n >> 10, hw = n & 1023;
    const float* px = x + (size_t)b * 262144 + hw;
    float s = 0.f;
#pragma unroll 8
    for (int c = 0; c < CDIM; c++) { float v = px[c * 1024]; s += v * v; }
    g_sx2[n] = s;
}

// ---------------------------------------------------------------------------
// Main distance GEMM + argmin. Tile: 128 tokens x 128 codes per CTA,
// 512 threads. Decomposition (breaks the smem-crossbar wall measured in
// R9: 128 wf/SM/cp == 128 cyc/cp fma floor):
//   warp w owns codes j = w*8..w*8+7  -> e loads are warp-uniform BROADCAST
//   lane tx owns tokens i = tx*4..+3  -> x loads are one conflict-free LDS.128
// Per cp per warp: 1 LDS.128 (x, 4 wf) + 2 LDS.128 broadcast (e, 2 wf)
// = 6 wf vs 8 before -> 96 wf/SM/cp at a 128 cyc/cp fma floor (75%).
// Accumulators: f32x2 pairs along tokens, acc[2][8] u64.
// Argmin: per-thread local best over its (4 tok x 8 j) slice per kt (k visited
// ascending -> first-min ties preserved), one cross-warp smem reduction at end
// with (d, k) lexicographic compare == reference first-argmin.
#define TM 128
#define TN 128
#define ES_STR 132                       // 128 + 4 pad floats per c-row
#define ES_BUF (64 * ES_STR)             // one chunk buffer (floats)
#define SMEM_MAIN (256 * 128 * 4 + 2 * ES_BUF * 4)   // 131072 + 67584 = 198656

extern __shared__ float smem[];

typedef unsigned long long u64;

__device__ __forceinline__ void fma2(u64& acc, u64 a, u64 b) {
    asm("fma.rn.f32x2 %0, %1, %2, %0;" : "+l"(acc) : "l"(a), "l"(b));
}
__device__ __forceinline__ u64 dup2(float v) {
    u64 r;
    asm("mov.b64 %0, {%1, %1};" : "=l"(r) : "f"(v));
    return r;
}
__device__ __forceinline__ float f2lo(u64 v) {
    return __uint_as_float((unsigned int)v);
}
__device__ __forceinline__ float f2hi(u64 v) {
    return __uint_as_float((unsigned int)(v >> 32));
}

__global__ __launch_bounds__(512, 1)
void k_main(const float* __restrict__ x, const float* __restrict__ cb,
            float* __restrict__ out) {
    float* xs = smem;               // [256][128] : xs[c][m]
    float* es = smem + 256 * 128;   // 2 buffers of [64][ES_STR] : es[c'][kk]

    int tid = threadIdx.x;
    int tx = tid & 31;              // lane: tokens i = tx*4 .. tx*4+3
    int w  = tid >> 5;              // warp: codes j = w*8 .. w*8+7
    int j0 = w * 8;
    int i0 = tx * 4;
    int m0 = blockIdx.x * TM;       // 1024 % 128 == 0 -> single batch b
    int bb = m0 >> 10, hw0 = m0 & 1023;
    const float* px = x + (size_t)bb * 262144 + hw0;

    // Load x tile into smem, transposed to [c][m]; coalesced float4 loads.
#pragma unroll 4
    for (int i = 0; i < 16; i++) {
        int idx4 = tid + i * 512;                // 0..8191 float4s
        int c = idx4 >> 5, m4 = (idx4 & 31) * 4;
        float4 v = *(const float4*)(px + c * 1024 + m4);
        *(float4*)(xs + c * 128 + m4) = v;
    }

    // Codebook chunk loader: chunk q covers codes [(q>>2)*128) and features
    // [(q&3)*64). 512 threads: kk = tid>>2 (code row), seg = tid&3 (16 floats).
    int kk = tid >> 2, seg = tid & 3;
    float4 pf[4];
    {   // prologue: chunk 0
        const float4* rowp = (const float4*)(cb + (size_t)kk * CDIM + seg * 16);
#pragma unroll
        for (int q4 = 0; q4 < 4; q4++) pf[q4] = rowp[q4];
        float* dst = es;                         // buffer 0
#pragma unroll
        for (int q4 = 0; q4 < 4; q4++) {
            int c0 = seg * 16 + q4 * 4;
            dst[(c0 + 0) * ES_STR + kk] = pf[q4].x;
            dst[(c0 + 1) * ES_STR + kk] = pf[q4].y;
            dst[(c0 + 2) * ES_STR + kk] = pf[q4].z;
            dst[(c0 + 3) * ES_STR + kk] = pf[q4].w;
        }
    }
    __syncthreads();

    float sx2v[4];
#pragma unroll
    for (int t = 0; t < 4; t++) sx2v[t] = g_sx2[m0 + i0 + t];

    float bestd[4]; int bestk[4];
#pragma unroll
    for (int t = 0; t < 4; t++) { bestd[t] = 3.4e38f; bestk[t] = 0x7fffffff; }

    for (int kt = 0; kt < KCODE / TN; kt++) {
        u64 acc[2][8];                  // [i-pair][j], lo = i even
#pragma unroll
        for (int p = 0; p < 2; p++)
#pragma unroll
            for (int j = 0; j < 8; j++) acc[p][j] = 0ull;

        for (int cch = 0; cch < 4; cch++) {
            int q = kt * 4 + cch;                // current chunk id
            if (q < 255) {                       // prefetch next chunk
                int qn = q + 1;
                int nk0 = (qn >> 2) << 7, nc0 = (qn & 3) << 6;
                const float4* rowp = (const float4*)(cb + (size_t)(nk0 + kk) * CDIM
                                                     + nc0 + seg * 16);
#pragma unroll
                for (int q4 = 0; q4 < 4; q4++) pf[q4] = rowp[q4];
            }

            const float* ebuf = es + (q & 1) * ES_BUF;
#pragma unroll 4
            for (int cp = 0; cp < 64; cp++) {
                const u64* xr = (const u64*)(xs + (cch * 64 + cp) * 128 + i0);
                u64 x0 = xr[0], x1 = xr[1];      // 4 tokens = 2 f32x2 pairs
                const float* er = ebuf + cp * ES_STR + j0;   // warp-uniform
                float4 ea = *(const float4*)(er);
                float4 eb4 = *(const float4*)(er + 4);
                u64 e0 = dup2(ea.x),  e1 = dup2(ea.y),
                    e2 = dup2(ea.z),  e3 = dup2(ea.w);
                u64 e4 = dup2(eb4.x), e5 = dup2(eb4.y),
                    e6 = dup2(eb4.z), e7 = dup2(eb4.w);
                fma2(acc[0][0], x0, e0); fma2(acc[1][0], x1, e0);
                fma2(acc[0][1], x0, e1); fma2(acc[1][1], x1, e1);
                fma2(acc[0][2], x0, e2); fma2(acc[1][2], x1, e2);
                fma2(acc[0][3], x0, e3); fma2(acc[1][3], x1, e3);
                fma2(acc[0][4], x0, e4); fma2(acc[1][4], x1, e4);
                fma2(acc[0][5], x0, e5); fma2(acc[1][5], x1, e5);
                fma2(acc[0][6], x0, e6); fma2(acc[1][6], x1, e6);
                fma2(acc[0][7], x0, e7); fma2(acc[1][7], x1, e7);
            }

            if (q < 255) {                       // store prefetched chunk
                float* dst = es + ((q + 1) & 1) * ES_BUF;
#pragma unroll
                for (int q4 = 0; q4 < 4; q4++) {
                    int c0 = seg * 16 + q4 * 4;
                    dst[(c0 + 0) * ES_STR + kk] = pf[q4].x;
                    dst[(c0 + 1) * ES_STR + kk] = pf[q4].y;
                    dst[(c0 + 2) * ES_STR + kk] = pf[q4].z;
                    dst[(c0 + 3) * ES_STR + kk] = pf[q4].w;
                }
                __syncthreads();
            }
        }

        // Per-kt local argmin over this thread's 4 tokens x 8 codes.
        // d = fl( fl(sx2 + se2_k) - 2*dot_k ), k visited ascending ->
        // strict < preserves first (lowest-k) minimum.
        int kbase = kt * TN + j0;
#pragma unroll
        for (int jj = 0; jj < 8; jj++) {
            float se2 = g_se2[kbase + jj];
#pragma unroll
            for (int t = 0; t < 4; t++) {
                u64 a = acc[t >> 1][jj];
                float dot = (t & 1) ? f2hi(a) : f2lo(a);
                float dv = __fsub_rn(__fadd_rn(sx2v[t], se2), 2.0f * dot);
                if (dv < bestd[t]) { bestd[t] = dv; bestk[t] = kbase + jj; }
            }
        }
    }

    // Cross-warp reduction: each token has 16 candidates (one per warp's
    // j-slice). Lexicographic (d, k) min == reference first-argmin.
    __syncthreads();                 // compute done; safe to reuse es area
    float* sd = es;                  // [128 tokens][16 warps]
    int*   sk = (int*)(es + 2048);
#pragma unroll
    for (int t = 0; t < 4; t++) {
        sd[(i0 + t) * 16 + w] = bestd[t];
        sk[(i0 + t) * 16 + w] = bestk[t];
    }
    __syncthreads();
    if (tid < 128) {
        float bd = 3.4e38f; int bk = 0x7fffffff;
#pragma unroll
        for (int w2 = 0; w2 < 16; w2++) {
            float d = sd[tid * 16 + w2]; int k2 = sk[tid * 16 + w2];
            if (d < bd || (d == bd && k2 < bk)) { bd = d; bk = k2; }
        }
        int n = m0 + tid;
        g_idx[n] = bk;
        out[IDX_OFF + n] = (float)bk;
        out[OH_OFF + (size_t)n * KCODE + bk] = 1.0f;
        atomicAdd(&g_hist[bk], 1);
    }
}

// ---------------------------------------------------------------------------
// x_quantized (with STE rounding emulated) + loss partial sums.
__global__ void k_xq(const float* __restrict__ x, const float* __restrict__ cb,
                     float* __restrict__ out) {
    int e = blockIdx.x * blockDim.x + threadIdx.x;   // < 8388608
    int b = e >> 18;
    int rem = e & 262143;
    int c = rem >> 10;
    int hw = rem & 1023;
    int n = (b << 10) + hw;
    int k = g_idx[n];
    float ev = cb[(size_t)k * CDIM + c];
    float xv = x[e];
    // straight-through: xt + fl(xq - xt), matching reference fp32 rounding
    out[XQ_OFF + e] = __fadd_rn(xv, __fsub_rn(ev, xv));

    float d1 = xv - ev;
    double s1 = (double)d1, s2 = (double)d1 * (double)d1;
#pragma unroll
    for (int o = 16; o > 0; o >>= 1) {
        s1 += __shfl_down_sync(0xffffffffu, s1, o);
        s2 += __shfl_down_sync(0xffffffffu, s2, o);
    }
    __shared__ double sh[64];
    int lane = threadIdx.x & 31, wp = threadIdx.x >> 5;
    if (lane == 0) { sh[wp] = s1; sh[wp + 32] = s2; }
    __syncthreads();
    if (wp == 0) {
        double a = sh[lane], bq = sh[lane + 32];
#pragma unroll
        for (int o = 16; o > 0; o >>= 1) {
            a  += __shfl_down_sync(0xffffffffu, a, o);
            bq += __shfl_down_sync(0xffffffffu, bq, o);
        }
        if (lane == 0) { g_part[2 * blockIdx.x] = a; g_part[2 * blockIdx.x + 1] = bq; }
    }
}

// ---------------------------------------------------------------------------
// Final scalars: loss + perplexity (deterministic fixed-tree reductions).
__global__ void k_final(float* __restrict__ out) {
    __shared__ double sa[256], sb[256], shh[256];
    int t = threadIdx.x;
    double a = 0.0, b = 0.0;
    for (int i = t; i < 8192; i += 256) { a += g_part[2 * i]; b += g_part[2 * i + 1]; }
    sa[t] = a; sb[t] = b;
    double h = 0.0;
    for (int i = t; i < KCODE; i += 256) {
        float p = (float)g_hist[i] * (1.0f / 32768.0f);
        h += (double)(p * logf(p + 1e-10f));
    }
    shh[t] = h;
    __syncthreads();
    for (int s = 128; s > 0; s >>= 1) {
        if (t < s) { sa[t] += sa[t + s]; sb[t] += sb[t + s]; shh[t] += shh[t + s]; }
        __syncthreads();
    }
    if (t == 0) {
        double loss = 0.25 * (sa[0] / (double)NE) + sb[0] / (double)NE;
        out[LOSS_OFF] = (float)loss;
        out[PERP_OFF] = (float)exp(-shh[0]);
    }
}

// ---------------------------------------------------------------------------
extern "C" void kernel_launch(void* const* d_in, const int* in_sizes, int n_in,
                              void* d_out, int out_size) {
    const float* x  = (const float*)d_in[0];   // [32,256,32,32]
    const float* cb = (const float*)d_in[1];   // [8192,256]
    float* out = (float*)d_out;

    // zero the one-hot region (poisoned to 0xAA by the harness)
    cudaMemsetAsync(out + OH_OFF, 0, (size_t)N_TOK * KCODE * sizeof(float));

    k_init<<<1, 256>>>();
    k_se2<<<KCODE / 8, 256>>>(cb);      // 8 warps/block, one warp per code
    k_sx2<<<N_TOK / 256, 256>>>(x);

    cudaFuncSetAttribute(k_main, cudaFuncAttributeMaxDynamicSharedMemorySize,
                         SMEM_MAIN);
    k_main<<<N_TOK / TM, 512, SMEM_MAIN>>>(x, cb, out);

    k_xq<<<NE / 1024, 1024>>>(x, cb, out);
    k_final<<<1, 256>>>(out);
}